// round 6
// baseline (speedup 1.0000x reference)
#include <cuda_runtime.h>
#include <cuda_bf16.h>
#include <cstdint>

#define B_    8
#define CIN   512
#define HW    4096
#define K9    4608

__device__ float g_xup[B_*CIN*HW];
__device__ float g_y1[B_*CIN*HW];
__device__ float g_wmod1[B_*CIN*K9];
__device__ float g_wmod2[B_*CIN*K9];
__device__ float g_wmod3[B_*3*CIN];
__device__ float g_styles[3*B_*CIN];

__device__ __forceinline__ float rtf(float x){
    uint32_t u; asm("cvt.rna.tf32.f32 %0, %1;" : "=r"(u) : "f"(x));
    return __uint_as_float(u);
}
__device__ __forceinline__ float lk(float v){ return v >= 0.f ? v : 0.2f*v; }

__device__ __forceinline__ void cp16(uint32_t dst, const float* src){
    asm volatile("cp.async.cg.shared.global [%0], [%1], 16;" :: "r"(dst), "l"(src));
}
__device__ __forceinline__ void cpcommit(){ asm volatile("cp.async.commit_group;"); }
__device__ __forceinline__ void cpwait0(){ asm volatile("cp.async.wait_group 0;"); }
__device__ __forceinline__ void cpwait1(){ asm volatile("cp.async.wait_group 1;"); }

__device__ __forceinline__ void mma_tf32(float* c, const uint32_t* a, const uint32_t* b){
    asm volatile("mma.sync.aligned.m16n8k8.row.col.f32.tf32.tf32.f32 "
        "{%0,%1,%2,%3},{%4,%5,%6,%7},{%8,%9},{%0,%1,%2,%3};"
        : "+f"(c[0]), "+f"(c[1]), "+f"(c[2]), "+f"(c[3])
        : "r"(a[0]), "r"(a[1]), "r"(a[2]), "r"(a[3]), "r"(b[0]), "r"(b[1]));
}

// bilinear x2 upsample (align_corners) 32->64, output tf32-rounded
__global__ void up2_kernel(const float* __restrict__ in, float* __restrict__ out){
    int idx = blockIdx.x*256 + threadIdx.x;
    int xo = idx & 63;
    int yo = (idx >> 6) & 63;
    int bc = idx >> 12;
    const float R = 31.0f/63.0f;
    float cy = yo * R; int y0 = (int)cy; float ty = cy - (float)y0; int y1 = min(y0+1, 31);
    float cx = xo * R; int x0 = (int)cx; float tx = cx - (float)x0; int x1 = min(x0+1, 31);
    const float* p = in + (size_t)bc*1024;
    float a = p[y0*32+x0], b = p[y0*32+x1], c = p[y1*32+x0], d = p[y1*32+x1];
    float v0 = a*(1.f-ty) + c*ty;
    float v1 = b*(1.f-ty) + d*ty;
    out[idx] = rtf(v0*(1.f-tx) + v1*tx);
}

__global__ void styles_kernel(const float* __restrict__ w,
    const float* __restrict__ A1w, const float* __restrict__ A1b,
    const float* __restrict__ A2w, const float* __restrict__ A2b,
    const float* __restrict__ A3w, const float* __restrict__ A3b,
    float* __restrict__ out)
{
    int idx = blockIdx.x*256 + threadIdx.x;    // 3*8*512
    int l = idx >> 12; int c = idx & 511; int b = (idx >> 9) & 7;
    const float* A    = (l==0) ? A1w : (l==1) ? A2w : A3w;
    const float* bias = (l==0) ? A1b : (l==1) ? A2b : A3b;
    const float* wb = w + b*512;
    const float* Ar = A + (size_t)c*512;
    float acc = 0.f;
    #pragma unroll 4
    for (int z=0; z<512; z++) acc += wb[z]*Ar[z];
    out[idx] = acc + bias[c];
}

// modulate + demodulate; one block per (b,co), 512 threads over ci
template<int KK, int ROUND>
__global__ void wmod_kernel(const float* __restrict__ W, const float* __restrict__ styles,
                            float* __restrict__ out, int CO)
{
    int b = blockIdx.x / CO, co = blockIdx.x - b*CO;
    int ci = threadIdx.x;
    float s = styles[b*512 + ci];
    float v[KK];
    const float* wp = W + (size_t)(co*512 + ci)*KK;
    float ss = 0.f;
    #pragma unroll
    for (int k=0;k<KK;k++){ v[k] = wp[k]*s; ss += v[k]*v[k]; }
    __shared__ float red[17];
    #pragma unroll
    for (int o=16;o>0;o>>=1) ss += __shfl_xor_sync(0xffffffffu, ss, o);
    int lane = ci & 31, wid = ci >> 5;
    if (lane==0) red[wid]=ss;
    __syncthreads();
    if (wid==0){
        float t = (lane<16) ? red[lane] : 0.f;
        #pragma unroll
        for (int o=8;o>0;o>>=1) t += __shfl_xor_sync(0xffffffffu, t, o);
        if (lane==0) red[16] = rsqrtf(t + 1e-8f);
    }
    __syncthreads();
    float d = red[16];
    float* op = out + ((size_t)(b*CO + co)*512 + ci)*KK;
    #pragma unroll
    for (int k=0;k<KK;k++){ float u = v[k]*d; op[k] = ROUND ? rtf(u) : u; }
}

#define BM   128
#define BN   128
#define NIT  64
#define AST  76
#define PST  72
#define AS_F (BM*AST)
#define PS_F (8*4*PST)
#define BUF_F (AS_F + PS_F)
#define CONV_SMEM (2*BUF_F*4)

template<int ROUND>
__global__ void __launch_bounds__(128)
conv3x3_kernel(const float* __restrict__ X, const float* __restrict__ Wm,
               const float* __restrict__ Bv, const float* __restrict__ noise,
               float* __restrict__ Y)
{
    extern __shared__ float smbuf[];
    const int tid = threadIdx.x;
    const int bx = blockIdx.x, my = blockIdx.y, bz = blockIdx.z;
    const int mBase = my*BM, nBase = bx*BN;
    const int y0 = bx*2;
    const float* Ag = Wm + ((size_t)bz*512 + mBase)*K9;
    const float* Xg = X + (size_t)bz*512*HW;

    {   // zero patch buffers once; halo cols/rows stay zero
        float* P0 = smbuf + AS_F;
        float* P1 = smbuf + BUF_F + AS_F;
        for (int i=tid; i<PS_F; i+=128){ P0[i]=0.f; P1[i]=0.f; }
    }
    __syncthreads();

    auto prefetch = [&](int it, int s){
        float* As = smbuf + s*BUF_F;
        float* Ps = As + AS_F;
        uint32_t sA = (uint32_t)__cvta_generic_to_shared(As);
        uint32_t sP = (uint32_t)__cvta_generic_to_shared(Ps);
        const float* a = Ag + it*72;
        #pragma unroll
        for (int i=0;i<18;i++){
            int e = tid + 128*i;
            int r = e / 18, c = e - r*18;
            cp16(sA + (uint32_t)(r*AST + c*4)*4u, a + (size_t)r*K9 + c*4);
        }
        const float* x = Xg + (size_t)(it*8)*HW;
        #pragma unroll
        for (int i=0;i<4;i++){
            int e = tid + 128*i;
            int ci = e >> 6, rem = e & 63, row = rem >> 4, v = rem & 15;
            int iy = y0 - 1 + row;
            if (iy >= 0 && iy < 64)
                cp16(sP + (uint32_t)((ci*4+row)*PST + 4 + v*4)*4u,
                     x + (size_t)ci*HW + iy*64 + v*4);
        }
        cpcommit();
    };

    const int lane = tid & 31, warp = tid >> 5;
    const int m0 = (warp >> 1)*64, n0 = (warp & 1)*64;
    const int gid = lane >> 2, tig = lane & 3;

    int pA[4];
    #pragma unroll
    for (int mi=0;mi<4;mi++) pA[mi] = (m0 + mi*16 + gid)*AST;
    int off0[9], off1[9];
    #pragma unroll
    for (int s=0;s<9;s++){
        int k0 = s*8 + tig;
        int ci = k0/9, r = k0 - ci*9, kh = r/3, kw = r - kh*3;
        off0[s] = (ci*4 + kh)*PST + kw + 3;
        int k1 = k0 + 4;
        ci = k1/9; r = k1 - ci*9; kh = r/3; kw = r - kh*3;
        off1[s] = (ci*4 + kh)*PST + kw + 3;
    }
    int nj[8];
    #pragma unroll
    for (int j=0;j<8;j++){
        int n = n0 + j*8 + gid;
        nj[j] = (n >> 6)*PST + (n & 63);
    }

    float acc[4][8][4];
    #pragma unroll
    for (int mi=0;mi<4;mi++)
        #pragma unroll
        for (int j=0;j<8;j++)
            #pragma unroll
            for (int q=0;q<4;q++) acc[mi][j][q] = 0.f;

    prefetch(0, 0);
    #pragma unroll 1
    for (int it=0; it<NIT; ++it){
        const int s = it & 1;
        if (it + 1 < NIT){ prefetch(it+1, s^1); cpwait1(); }
        else             { cpwait0(); }
        __syncthreads();
        const float* As = smbuf + s*BUF_F;
        const float* Ps = As + AS_F;
        #pragma unroll
        for (int st=0; st<9; ++st){
            uint32_t a[4][4], b[8][2];
            const int kk = st*8 + tig;
            #pragma unroll
            for (int mi=0;mi<4;mi++){
                a[mi][0] = __float_as_uint(As[pA[mi] + kk]);
                a[mi][1] = __float_as_uint(As[pA[mi] + 8*AST + kk]);
                a[mi][2] = __float_as_uint(As[pA[mi] + kk + 4]);
                a[mi][3] = __float_as_uint(As[pA[mi] + 8*AST + kk + 4]);
            }
            #pragma unroll
            for (int j=0;j<8;j++){
                b[j][0] = __float_as_uint(Ps[off0[st] + nj[j]]);
                b[j][1] = __float_as_uint(Ps[off1[st] + nj[j]]);
            }
            #pragma unroll
            for (int mi=0;mi<4;mi++)
                #pragma unroll
                for (int j=0;j<8;j++)
                    mma_tf32(acc[mi][j], a[mi], b[j]);
        }
        __syncthreads();
    }

    const float* nz = noise + bz*HW;
    float* Yb = Y + (size_t)bz*512*HW;
    #pragma unroll
    for (int mi=0;mi<4;mi++){
        int co0 = mBase + m0 + mi*16 + gid;
        int co1 = co0 + 8;
        float bb0 = Bv[co0], bb1 = Bv[co1];
        #pragma unroll
        for (int j=0;j<8;j++){
            int cg = nBase + n0 + j*8 + 2*tig;
            float nz0 = nz[cg], nz1 = nz[cg+1];
            float v00 = lk(acc[mi][j][0] + bb0*nz0);
            float v01 = lk(acc[mi][j][1] + bb0*nz1);
            float v10 = lk(acc[mi][j][2] + bb1*nz0);
            float v11 = lk(acc[mi][j][3] + bb1*nz1);
            if (ROUND){ v00=rtf(v00); v01=rtf(v01); v10=rtf(v10); v11=rtf(v11); }
            *reinterpret_cast<float2*>(Yb + (size_t)co0*HW + cg) = make_float2(v00, v01);
            *reinterpret_cast<float2*>(Yb + (size_t)co1*HW + cg) = make_float2(v10, v11);
        }
    }
}

// toRGB 1x1 conv 512->3 + noise + leaky + inline up2(rgb) skip
__global__ void rgb_kernel(const float* __restrict__ xo, const float* __restrict__ wm3,
    const float* __restrict__ rgbin, const float* __restrict__ B3,
    const float* __restrict__ noise3, float* __restrict__ out)
{
    __shared__ float ws[1536];
    int b = blockIdx.x >> 4;
    int pix = ((blockIdx.x & 15) << 8) + threadIdx.x;
    const float* wsrc = wm3 + b*1536;
    for (int i=threadIdx.x;i<1536;i+=256) ws[i]=wsrc[i];
    __syncthreads();
    float a0=0.f, a1=0.f, a2=0.f;
    const float* xp = xo + (size_t)b*512*HW + pix;
    #pragma unroll 8
    for (int ci=0;ci<512;ci++){
        float v = xp[(size_t)ci*HW];
        a0 += v*ws[ci]; a1 += v*ws[512+ci]; a2 += v*ws[1024+ci];
    }
    float nzv = noise3[b*HW + pix];
    int xoI = pix & 63, yoI = pix >> 6;
    const float R = 31.0f/63.0f;
    float cy = yoI*R; int y0 = (int)cy; float ty = cy - (float)y0; int y1 = min(y0+1,31);
    float cx = xoI*R; int x0 = (int)cx; float tx = cx - (float)x0; int x1 = min(x0+1,31);
    float accv[3] = {a0,a1,a2};
    #pragma unroll
    for (int c=0;c<3;c++){
        const float* p = rgbin + (size_t)(b*3+c)*1024;
        float aa=p[y0*32+x0], bb=p[y0*32+x1], cc=p[y1*32+x0], dd=p[y1*32+x1];
        float v0 = aa*(1.f-ty)+cc*ty, v1 = bb*(1.f-ty)+dd*ty;
        float up = v0*(1.f-tx)+v1*tx;
        out[(size_t)(b*3+c)*HW + pix] = up + lk(accv[c] + B3[c]*nzv);
    }
}

extern "C" void kernel_launch(void* const* d_in, const int* in_sizes, int n_in,
                              void* d_out, int out_size)
{
    const float* x       = (const float*)d_in[0];
    const float* rgb     = (const float*)d_in[1];
    const float* w       = (const float*)d_in[2];
    const float* noise1  = (const float*)d_in[3];
    const float* noise2  = (const float*)d_in[4];
    const float* noise3  = (const float*)d_in[5];
    const float* weight1 = (const float*)d_in[6];
    const float* A1w     = (const float*)d_in[7];
    const float* A1b     = (const float*)d_in[8];
    const float* B1      = (const float*)d_in[9];
    const float* weight2 = (const float*)d_in[10];
    const float* A2w     = (const float*)d_in[11];
    const float* A2b     = (const float*)d_in[12];
    const float* B2      = (const float*)d_in[13];
    const float* weight3 = (const float*)d_in[14];
    const float* A3w     = (const float*)d_in[15];
    const float* A3b     = (const float*)d_in[16];
    const float* B3      = (const float*)d_in[17];

    float* xout   = (float*)d_out;                       // [8,512,64,64]
    float* rgbout = xout + (size_t)B_*CIN*HW;            // [8,3,64,64]

    float *xup, *y1, *wm1, *wm2, *wm3, *sty;
    cudaGetSymbolAddress((void**)&xup, g_xup);
    cudaGetSymbolAddress((void**)&y1,  g_y1);
    cudaGetSymbolAddress((void**)&wm1, g_wmod1);
    cudaGetSymbolAddress((void**)&wm2, g_wmod2);
    cudaGetSymbolAddress((void**)&wm3, g_wmod3);
    cudaGetSymbolAddress((void**)&sty, g_styles);

    cudaFuncSetAttribute(conv3x3_kernel<1>, cudaFuncAttributeMaxDynamicSharedMemorySize, CONV_SMEM);
    cudaFuncSetAttribute(conv3x3_kernel<0>, cudaFuncAttributeMaxDynamicSharedMemorySize, CONV_SMEM);

    up2_kernel<<<65536, 256>>>(x, xup);
    styles_kernel<<<48, 256>>>(w, A1w, A1b, A2w, A2b, A3w, A3b, sty);
    wmod_kernel<9,1><<<B_*512, 512>>>(weight1, sty,            wm1, 512);
    wmod_kernel<9,1><<<B_*512, 512>>>(weight2, sty + B_*CIN,   wm2, 512);
    wmod_kernel<1,0><<<B_*3,   512>>>(weight3, sty + 2*B_*CIN, wm3, 3);

    dim3 cgrid(32, 4, B_);
    conv3x3_kernel<1><<<cgrid, 128, CONV_SMEM>>>(xup, wm1, B1, noise1, y1);
    conv3x3_kernel<0><<<cgrid, 128, CONV_SMEM>>>(y1,  wm2, B2, noise2, xout);

    rgb_kernel<<<B_*16, 256>>>(xout, wm3, rgb, B3, noise3, rgbout);
}

// round 11
// speedup vs baseline: 1.7985x; 1.7985x over previous
#include <cuda_runtime.h>
#include <cuda_fp16.h>
#include <cstdint>

#define B_    8
#define CIN   512
#define HW    4096

// scratch
__device__ __half g_xup[B_*CIN*HW];        // paired layout [b][ci/2][y][x][2]
__device__ __half g_y1[B_*CIN*HW];         // same layout
__device__ __half g_wmod1[B_*CIN*CIN*9];   // [b][co][tap][ci]
__device__ __half g_wmod2[B_*CIN*CIN*9];
__device__ float  g_wmod3[B_*3*CIN];
__device__ float  g_styles[3*B_*CIN];

__device__ __forceinline__ float lk(float v){ return v >= 0.f ? v : 0.2f*v; }

__device__ __forceinline__ void cp16(uint32_t dst, const void* src){
    asm volatile("cp.async.cg.shared.global [%0], [%1], 16;" :: "r"(dst), "l"(src));
}
__device__ __forceinline__ void cpcommit(){ asm volatile("cp.async.commit_group;"); }
__device__ __forceinline__ void cpwait0(){ asm volatile("cp.async.wait_group 0;"); }
__device__ __forceinline__ void cpwait1(){ asm volatile("cp.async.wait_group 1;"); }

__device__ __forceinline__ void mma_f16(float* c, const uint32_t* a, const uint32_t* b){
    asm volatile("mma.sync.aligned.m16n8k16.row.col.f32.f16.f16.f32 "
        "{%0,%1,%2,%3},{%4,%5,%6,%7},{%8,%9},{%0,%1,%2,%3};"
        : "+f"(c[0]), "+f"(c[1]), "+f"(c[2]), "+f"(c[3])
        : "r"(a[0]), "r"(a[1]), "r"(a[2]), "r"(a[3]), "r"(b[0]), "r"(b[1]));
}

// bilinear x2 upsample 32->64 (align_corners), write fp16 channel-pair layout
__global__ void up2_kernel(const float* __restrict__ in, __half* __restrict__ out){
    int idx = blockIdx.x*256 + threadIdx.x;
    int xo = idx & 63;
    int yo = (idx >> 6) & 63;
    int bc = idx >> 12;                           // b*512 + ci
    const float R = 31.0f/63.0f;
    float cy = yo * R; int y0 = (int)cy; float ty = cy - (float)y0; int y1 = min(y0+1, 31);
    float cx = xo * R; int x0 = (int)cx; float tx = cx - (float)x0; int x1 = min(x0+1, 31);
    const float* p = in + (size_t)bc*1024;
    float a = p[y0*32+x0], b = p[y0*32+x1], c = p[y1*32+x0], d = p[y1*32+x1];
    float v0 = a*(1.f-ty) + c*ty;
    float v1 = b*(1.f-ty) + d*ty;
    float v  = v0*(1.f-tx) + v1*tx;
    int ci = bc & 511, bb = bc >> 9;
    size_t dst = (((size_t)(bb*256 + (ci>>1))*HW) + (yo*64+xo))*2 + (ci&1);
    out[dst] = __float2half_rn(v);
}

__global__ void styles_kernel(const float* __restrict__ w,
    const float* __restrict__ A1w, const float* __restrict__ A1b,
    const float* __restrict__ A2w, const float* __restrict__ A2b,
    const float* __restrict__ A3w, const float* __restrict__ A3b,
    float* __restrict__ out)
{
    int idx = blockIdx.x*256 + threadIdx.x;    // 3*8*512
    int l = idx >> 12; int c = idx & 511; int b = (idx >> 9) & 7;
    const float* A    = (l==0) ? A1w : (l==1) ? A2w : A3w;
    const float* bias = (l==0) ? A1b : (l==1) ? A2b : A3b;
    const float* wb = w + b*512;
    const float* Ar = A + (size_t)c*512;
    float acc = 0.f;
    #pragma unroll 4
    for (int z=0; z<512; z++) acc += wb[z]*Ar[z];
    out[idx] = acc + bias[c];
}

// modulate + demodulate 3x3 weights -> fp16 [b][co][tap][ci]
__global__ void wmod9_kernel(const float* __restrict__ W, const float* __restrict__ styles,
                             __half* __restrict__ out)
{
    int b = blockIdx.x >> 9, co = blockIdx.x & 511;
    int ci = threadIdx.x;
    float s = styles[b*512 + ci];
    float v[9];
    const float* wp = W + (size_t)(co*512 + ci)*9;
    float ss = 0.f;
    #pragma unroll
    for (int k=0;k<9;k++){ v[k] = wp[k]*s; ss += v[k]*v[k]; }
    __shared__ float red[17];
    #pragma unroll
    for (int o=16;o>0;o>>=1) ss += __shfl_xor_sync(0xffffffffu, ss, o);
    int lane = ci & 31, wid = ci >> 5;
    if (lane==0) red[wid]=ss;
    __syncthreads();
    if (wid==0){
        float t = (lane<16) ? red[lane] : 0.f;
        #pragma unroll
        for (int o=8;o>0;o>>=1) t += __shfl_xor_sync(0xffffffffu, t, o);
        if (lane==0) red[16] = rsqrtf(t + 1e-8f);
    }
    __syncthreads();
    float d = red[16];
    __half* op = out + ((size_t)(b*512 + co)*9)*512 + ci;
    #pragma unroll
    for (int k=0;k<9;k++) op[(size_t)k*512] = __float2half_rn(v[k]*d);
}

// modulate + demodulate 1x1 toRGB weights (fp32)
__global__ void wmod1_kernel(const float* __restrict__ W, const float* __restrict__ styles,
                             float* __restrict__ out)
{
    int b = blockIdx.x / 3, co = blockIdx.x - b*3;
    int ci = threadIdx.x;
    float s = styles[b*512 + ci];
    float v = W[(size_t)co*512 + ci] * s;
    float ss = v*v;
    __shared__ float red[17];
    #pragma unroll
    for (int o=16;o>0;o>>=1) ss += __shfl_xor_sync(0xffffffffu, ss, o);
    int lane = ci & 31, wid = ci >> 5;
    if (lane==0) red[wid]=ss;
    __syncthreads();
    if (wid==0){
        float t = (lane<16) ? red[lane] : 0.f;
        #pragma unroll
        for (int o=8;o>0;o>>=1) t += __shfl_xor_sync(0xffffffffu, t, o);
        if (lane==0) red[16] = rsqrtf(t + 1e-8f);
    }
    __syncthreads();
    out[(size_t)(b*3 + co)*512 + ci] = v * red[16];
}

// ---------------- conv: implicit GEMM, fp16 m16n8k16 ----------------
// K order: k = tap*512 + ci. Per iter: 16-ci block, 9 taps = 9 k16 steps.
#define BM    128
#define BN    128
#define NIT   32
#define ASTW  76      // A row stride in u32 words (152 halfs)
#define RST   72      // patch row stride in u32 words (16B-aligned rows)
#define CBS   296     // cipair block stride = 4*RST + 8 pad (mod 32 == 8: conflict-free)
#define AS_W  (BM*ASTW)          // 9728 words
#define PS_W  (8*CBS)            // 2368 words
#define BUF_W (AS_W + PS_W)      // 12096 words
#define CONV_SMEM (2*BUF_W*4)    // 96768 B

template<int HALF_OUT>
__global__ void __launch_bounds__(128)
conv3x3_kernel(const __half* __restrict__ Xp, const __half* __restrict__ Wm,
               const float* __restrict__ Bv, const float* __restrict__ noise,
               void* __restrict__ Yv)
{
    extern __shared__ uint32_t smw[];
    const int tid = threadIdx.x;
    const int bx = blockIdx.x, my = blockIdx.y, bz = blockIdx.z;
    const int mBase = my*BM, nBase = bx*BN;
    const int y0 = bx*2;
    const __half* Ag = Wm + ((size_t)(bz*512 + mBase)*9)*512;   // [co][tap][ci]
    const __half* Xg = Xp + (size_t)bz*256*HW*2;                // [cipair][y][x][2]

    {   // zero patch buffers once (halo + pads stay zero)
        uint32_t* P0 = smw + AS_W;
        uint32_t* P1 = smw + BUF_W + AS_W;
        for (int i=tid; i<PS_W; i+=128){ P0[i]=0u; P1[i]=0u; }
    }
    __syncthreads();

    auto prefetch = [&](int it, int s){
        uint32_t* As = smw + s*BUF_W;
        uint32_t* Ps = As + AS_W;
        uint32_t sA = (uint32_t)__cvta_generic_to_shared(As);
        uint32_t sP = (uint32_t)__cvta_generic_to_shared(Ps);
        // A: 128 co x 9 taps x 16 ci halfs = 2304 x 16B
        #pragma unroll
        for (int i=0;i<18;i++){
            int e = tid + 128*i;
            int r = e / 18, c = e - r*18;
            int tap = c >> 1, hf = c & 1;
            cp16(sA + (uint32_t)(r*ASTW + tap*8 + hf*4)*4u,
                 Ag + ((size_t)r*9 + tap)*512 + it*16 + hf*8);
        }
        // patch: 8 cipair x 4 rows x 64 px (2 halfs each) = 512 x 16B
        #pragma unroll
        for (int i=0;i<4;i++){
            int e = tid + 128*i;
            int cp = e >> 6, rem = e & 63, row = rem >> 4, v = rem & 15;
            int iy = y0 - 1 + row;
            if (iy >= 0 && iy < 64)
                cp16(sP + (uint32_t)(cp*CBS + row*RST + 4 + v*4)*4u,
                     Xg + ((size_t)(it*8+cp)*HW + iy*64 + v*4)*2);
        }
        cpcommit();
    };

    const int lane = tid & 31, warp = tid >> 5;
    const int m0 = (warp >> 1)*64, n0 = (warp & 1)*64;
    const int gid = lane >> 2, tig = lane & 3;

    int pA[4];
    #pragma unroll
    for (int mi=0;mi<4;mi++) pA[mi] = (m0 + mi*16 + gid)*ASTW;
    int offB[9];
    #pragma unroll
    for (int t9=0;t9<9;t9++){
        int kh = t9/3, kw = t9 - kh*3;
        offB[t9] = kh*RST + kw + 3;
    }
    const int bB = tig*CBS;                     // cipair = tig
    int nj[8];
    #pragma unroll
    for (int j=0;j<8;j++){
        int n = n0 + j*8 + gid;
        nj[j] = (n >> 6)*RST + (n & 63);
    }

    float acc[4][8][4];
    #pragma unroll
    for (int mi=0;mi<4;mi++)
        #pragma unroll
        for (int j=0;j<8;j++)
            #pragma unroll
            for (int q=0;q<4;q++) acc[mi][j][q] = 0.f;

    prefetch(0, 0);
    #pragma unroll 1
    for (int it=0; it<NIT; ++it){
        const int s = it & 1;
        if (it + 1 < NIT){ prefetch(it+1, s^1); cpwait1(); }
        else             { cpwait0(); }
        __syncthreads();
        const uint32_t* As = smw + s*BUF_W;
        const uint32_t* Ps = As + AS_W;
        #pragma unroll
        for (int st=0; st<9; ++st){
            uint32_t a[4][4], b[8][2];
            const int ka = st*8 + tig;
            #pragma unroll
            for (int mi=0;mi<4;mi++){
                a[mi][0] = As[pA[mi] + ka];
                a[mi][1] = As[pA[mi] + 8*ASTW + ka];
                a[mi][2] = As[pA[mi] + ka + 4];
                a[mi][3] = As[pA[mi] + 8*ASTW + ka + 4];
            }
            const int ob = bB + offB[st];
            #pragma unroll
            for (int j=0;j<8;j++){
                b[j][0] = Ps[ob + nj[j]];
                b[j][1] = Ps[ob + nj[j] + 4*CBS];   // cipair tig+4
            }
            #pragma unroll
            for (int mi=0;mi<4;mi++)
                #pragma unroll
                for (int j=0;j<8;j++)
                    mma_f16(acc[mi][j], a[mi], b[j]);
        }
        __syncthreads();
    }

    const float* nz = noise + bz*HW;
    #pragma unroll
    for (int mi=0;mi<4;mi++){
        int co0 = mBase + m0 + mi*16 + gid;
        int co1 = co0 + 8;
        float bb0 = Bv[co0], bb1 = Bv[co1];
        #pragma unroll
        for (int j=0;j<8;j++){
            int cg = nBase + n0 + j*8 + 2*tig;
            float nz0 = nz[cg], nz1 = nz[cg+1];
            float v00 = lk(acc[mi][j][0] + bb0*nz0);
            float v01 = lk(acc[mi][j][1] + bb0*nz1);
            float v10 = lk(acc[mi][j][2] + bb1*nz0);
            float v11 = lk(acc[mi][j][3] + bb1*nz1);
            if (HALF_OUT){
                __half* Yh = (__half*)Yv + (size_t)bz*256*HW*2;
                size_t a0 = ((size_t)(co0>>1)*HW)*2 + (co0&1);
                size_t a1 = ((size_t)(co1>>1)*HW)*2 + (co1&1);
                Yh[a0 + (size_t)cg*2]     = __float2half_rn(v00);
                Yh[a0 + (size_t)(cg+1)*2] = __float2half_rn(v01);
                Yh[a1 + (size_t)cg*2]     = __float2half_rn(v10);
                Yh[a1 + (size_t)(cg+1)*2] = __float2half_rn(v11);
            } else {
                float* Yb = (float*)Yv + (size_t)bz*512*HW;
                *reinterpret_cast<float2*>(Yb + (size_t)co0*HW + cg) = make_float2(v00, v01);
                *reinterpret_cast<float2*>(Yb + (size_t)co1*HW + cg) = make_float2(v10, v11);
            }
        }
    }
}

// toRGB 1x1 conv 512->3 + noise + leaky + inline up2(rgb) skip
__global__ void rgb_kernel(const float* __restrict__ xo, const float* __restrict__ wm3,
    const float* __restrict__ rgbin, const float* __restrict__ B3,
    const float* __restrict__ noise3, float* __restrict__ out)
{
    __shared__ float ws[1536];
    int b = blockIdx.x >> 4;
    int pix = ((blockIdx.x & 15) << 8) + threadIdx.x;
    const float* wsrc = wm3 + b*1536;
    for (int i=threadIdx.x;i<1536;i+=256) ws[i]=wsrc[i];
    __syncthreads();
    float a0=0.f, a1=0.f, a2=0.f;
    const float* xp = xo + (size_t)b*512*HW + pix;
    #pragma unroll 8
    for (int ci=0;ci<512;ci++){
        float v = xp[(size_t)ci*HW];
        a0 += v*ws[ci]; a1 += v*ws[512+ci]; a2 += v*ws[1024+ci];
    }
    float nzv = noise3[b*HW + pix];
    int xoI = pix & 63, yoI = pix >> 6;
    const float R = 31.0f/63.0f;
    float cy = yoI*R; int y0 = (int)cy; float ty = cy - (float)y0; int y1 = min(y0+1,31);
    float cx = xoI*R; int x0 = (int)cx; float tx = cx - (float)x0; int x1 = min(x0+1,31);
    float accv[3] = {a0,a1,a2};
    #pragma unroll
    for (int c=0;c<3;c++){
        const float* p = rgbin + (size_t)(b*3+c)*1024;
        float aa=p[y0*32+x0], bb=p[y0*32+x1], cc=p[y1*32+x0], dd=p[y1*32+x1];
        float v0 = aa*(1.f-ty)+cc*ty, v1 = bb*(1.f-ty)+dd*ty;
        float up = v0*(1.f-tx)+v1*tx;
        out[(size_t)(b*3+c)*HW + pix] = up + lk(accv[c] + B3[c]*nzv);
    }
}

extern "C" void kernel_launch(void* const* d_in, const int* in_sizes, int n_in,
                              void* d_out, int out_size)
{
    const float* x       = (const float*)d_in[0];
    const float* rgb     = (const float*)d_in[1];
    const float* w       = (const float*)d_in[2];
    const float* noise1  = (const float*)d_in[3];
    const float* noise2  = (const float*)d_in[4];
    const float* noise3  = (const float*)d_in[5];
    const float* weight1 = (const float*)d_in[6];
    const float* A1w     = (const float*)d_in[7];
    const float* A1b     = (const float*)d_in[8];
    const float* B1      = (const float*)d_in[9];
    const float* weight2 = (const float*)d_in[10];
    const float* A2w     = (const float*)d_in[11];
    const float* A2b     = (const float*)d_in[12];
    const float* B2      = (const float*)d_in[13];
    const float* weight3 = (const float*)d_in[14];
    const float* A3w     = (const float*)d_in[15];
    const float* A3b     = (const float*)d_in[16];
    const float* B3      = (const float*)d_in[17];

    float* xout   = (float*)d_out;                       // [8,512,64,64]
    float* rgbout = xout + (size_t)B_*CIN*HW;            // [8,3,64,64]

    __half *xup, *y1, *wm1, *wm2;
    float *wm3, *sty;
    cudaGetSymbolAddress((void**)&xup, g_xup);
    cudaGetSymbolAddress((void**)&y1,  g_y1);
    cudaGetSymbolAddress((void**)&wm1, g_wmod1);
    cudaGetSymbolAddress((void**)&wm2, g_wmod2);
    cudaGetSymbolAddress((void**)&wm3, g_wmod3);
    cudaGetSymbolAddress((void**)&sty, g_styles);

    cudaFuncSetAttribute(conv3x3_kernel<1>, cudaFuncAttributeMaxDynamicSharedMemorySize, CONV_SMEM);
    cudaFuncSetAttribute(conv3x3_kernel<0>, cudaFuncAttributeMaxDynamicSharedMemorySize, CONV_SMEM);

    up2_kernel<<<65536, 256>>>(x, xup);
    styles_kernel<<<48, 256>>>(w, A1w, A1b, A2w, A2b, A3w, A3b, sty);
    wmod9_kernel<<<B_*512, 512>>>(weight1, sty,            wm1);
    wmod9_kernel<<<B_*512, 512>>>(weight2, sty + B_*CIN,   wm2);
    wmod1_kernel<<<B_*3,   512>>>(weight3, sty + 2*B_*CIN, wm3);

    dim3 cgrid(32, 4, B_);
    conv3x3_kernel<1><<<cgrid, 128, CONV_SMEM>>>(xup, wm1, B1, noise1, (void*)y1);
    conv3x3_kernel<0><<<cgrid, 128, CONV_SMEM>>>(y1,  wm2, B2, noise2, (void*)xout);

    rgb_kernel<<<B_*16, 256>>>(xout, wm3, rgb, B3, noise3, rgbout);
}